// round 2
// baseline (speedup 1.0000x reference)
#include <cuda_runtime.h>
#include <math.h>

// Row-normalize: out[b, r, c] = adj[b, r, c] / sum_c adj[b, r, c]
// adj: [2, 32, 1024, 1024] float32. 65536 rows of 1024 floats.
// One CTA per row, 256 threads, one float4 per thread (read-once/write-once).

static constexpr int ROW_LEN = 1024;
static constexpr int THREADS = 256;   // 1024 / 4 floats per thread

__global__ __launch_bounds__(THREADS)
void normalizer_kernel(const float* __restrict__ in, float* __restrict__ out) {
    const long long row = blockIdx.x;              // 0 .. 65535
    const long long base = row * ROW_LEN;
    const int tid = threadIdx.x;

    // One float4 per thread
    const float4* in4 = reinterpret_cast<const float4*>(in + base);
    float4 v = in4[tid];

    float s = v.x + v.y + v.z + v.w;

    // Warp reduce
    #pragma unroll
    for (int off = 16; off > 0; off >>= 1)
        s += __shfl_xor_sync(0xFFFFFFFFu, s, off);

    __shared__ float warp_sums[THREADS / 32];
    __shared__ float inv_shared;
    const int lane = tid & 31;
    const int wid  = tid >> 5;
    if (lane == 0) warp_sums[wid] = s;
    __syncthreads();

    if (wid == 0) {
        float t = (lane < THREADS / 32) ? warp_sums[lane] : 0.0f;
        #pragma unroll
        for (int off = 4; off > 0; off >>= 1)
            t += __shfl_xor_sync(0xFFFFFFFFu, t, off);
        if (lane == 0) {
            float inv = 1.0f / t;
            inv_shared = isfinite(inv) ? inv : 0.0f;
        }
    }
    __syncthreads();

    const float inv = inv_shared;
    v.x *= inv; v.y *= inv; v.z *= inv; v.w *= inv;

    float4* out4 = reinterpret_cast<float4*>(out + base);
    out4[tid] = v;
}

extern "C" void kernel_launch(void* const* d_in, const int* in_sizes, int n_in,
                              void* d_out, int out_size) {
    const float* adj = (const float*)d_in[0];
    float* out = (float*)d_out;
    const long long total = (long long)in_sizes[0];      // 2*32*1024*1024
    const int n_rows = (int)(total / ROW_LEN);            // 65536
    normalizer_kernel<<<n_rows, THREADS>>>(adj, out);
}

// round 3
// speedup vs baseline: 1.1007x; 1.1007x over previous
#include <cuda_runtime.h>
#include <math.h>

// Row-normalize: out[r, c] = in[r, c] / sum_c in[r, c]
// 65536 rows of 1024 floats. One WARP per row:
//   each lane loads 8 float4 (front-batched, MLP=8), warp-shuffle reduce,
//   scale in registers, 8 float4 stores. No __syncthreads, no smem.

static constexpr int ROW_LEN    = 1024;
static constexpr int V4_PER_ROW = ROW_LEN / 4;     // 256 float4 per row
static constexpr int V4_PER_LANE = V4_PER_ROW / 32; // 8 float4 per lane
static constexpr int THREADS    = 256;              // 8 warps per CTA
static constexpr int WARPS      = THREADS / 32;

__global__ __launch_bounds__(THREADS)
void normalizer_kernel(const float* __restrict__ in, float* __restrict__ out) {
    const int lane = threadIdx.x & 31;
    const int wid  = threadIdx.x >> 5;
    const long long row  = (long long)blockIdx.x * WARPS + wid;  // 0 .. 65535
    const long long base4 = row * V4_PER_ROW;                    // float4 index

    const float4* in4  = reinterpret_cast<const float4*>(in)  + base4 + lane;
    float4*       out4 = reinterpret_cast<float4*>(out)       + base4 + lane;

    // Front-batched loads: 8 independent LDG.128 in flight per lane.
    float4 v[V4_PER_LANE];
    #pragma unroll
    for (int i = 0; i < V4_PER_LANE; i++)
        v[i] = in4[i * 32];

    // Per-lane partial sum
    float s = 0.0f;
    #pragma unroll
    for (int i = 0; i < V4_PER_LANE; i++)
        s += (v[i].x + v[i].y) + (v[i].z + v[i].w);

    // Warp reduce (full warp participates)
    #pragma unroll
    for (int off = 16; off > 0; off >>= 1)
        s += __shfl_xor_sync(0xFFFFFFFFu, s, off);

    float inv = 1.0f / s;
    inv = isfinite(inv) ? inv : 0.0f;

    #pragma unroll
    for (int i = 0; i < V4_PER_LANE; i++) {
        v[i].x *= inv; v[i].y *= inv; v[i].z *= inv; v[i].w *= inv;
        out4[i * 32] = v[i];
    }
}

extern "C" void kernel_launch(void* const* d_in, const int* in_sizes, int n_in,
                              void* d_out, int out_size) {
    const float* adj = (const float*)d_in[0];
    float* out = (float*)d_out;
    const long long total = (long long)in_sizes[0];          // 2*32*1024*1024
    const int n_rows = (int)(total / ROW_LEN);                // 65536
    const int n_blocks = n_rows / WARPS;                      // 8192
    normalizer_kernel<<<n_blocks, THREADS>>>(adj, out);
}